// round 15
// baseline (speedup 1.0000x reference)
#include <cuda_runtime.h>
#include <cuda_fp16.h>
#include <cstdint>

#define NN 1024
#define SA (5.0f / 127.0f)
#define INV_SA (127.0f / 5.0f)

// ---------------- scratch (device globals; no allocs) ----------------
__device__ float g_pre1[NN * 128];        // [j][m]
__device__ float g_pre2g[NN * 128];
__device__ float g_vals[NN * 128];        // [j][c]
__device__ float g_skip[NN * 128];
__device__ float g_gterm[128];
__device__ float g_logits[(size_t)8 * NN * NN];   // [i][h][j]
__device__ __half g_probs[(size_t)8 * NN * NN];   // normalized softmax probs, fp16
__device__ char  g_WeQ[128 * 128];                // We^T quantized s8: [n][k]
__device__ float g_sB;

// ---------------- helpers ----------------
__device__ __forceinline__ unsigned h2u(__half2 h) { return *(unsigned*)&h; }
__device__ __forceinline__ unsigned quant4(float4 f, float inv) {
    int i0 = __float2int_rn(f.x * inv);
    int i1 = __float2int_rn(f.y * inv);
    int i2 = __float2int_rn(f.z * inv);
    int i3 = __float2int_rn(f.w * inv);
    unsigned t, d;
    asm("cvt.pack.sat.s8.s32.b32 %0, %1, %2, 0;"  : "=r"(t) : "r"(i3), "r"(i2));
    asm("cvt.pack.sat.s8.s32.b32 %0, %1, %2, %3;" : "=r"(d) : "r"(i1), "r"(i0), "r"(t));
    return d;   // bytes LSB->MSB: i0, i1, i2, i3
}

// ---------------- K0 ----------------
__global__ void k0_gterm(const float* __restrict__ gf, const float* __restrict__ Wg,
                         const float* __restrict__ bg, const float* __restrict__ be) {
    int m = threadIdx.x;
    float a = bg[m] + be[m];
#pragma unroll 8
    for (int k = 0; k < 128; k++) a += gf[k] * Wg[k * 128 + m];
    g_gterm[m] = a;
}

// ---------------- K0b: quantize We -> s8 (exact max scale) ----------------
__global__ __launch_bounds__(256) void k_quantWe(const float* __restrict__ We) {
    __shared__ float red[256];
    int tid = threadIdx.x;
    float mx = 0.f;
    for (int e = tid; e < 16384; e += 256) mx = fmaxf(mx, fabsf(We[e]));
    red[tid] = mx;
    __syncthreads();
    for (int s = 128; s > 0; s >>= 1) {
        if (tid < s) red[tid] = fmaxf(red[tid], red[tid + s]);
        __syncthreads();
    }
    float m = red[0];
    if (tid == 0) g_sB = m / 127.0f;
    float inv = 127.0f / m;
    for (int e = tid; e < 16384; e += 256) {
        int k = e >> 7, n = e & 127;
        int q = __float2int_rn(We[k * 128 + n] * inv);
        q = max(-127, min(127, q));
        g_WeQ[n * 128 + k] = (char)q;
    }
}

// ---------------- K1 (fused 4 projections) ----------------
__global__ __launch_bounds__(256) void k1_fused(const float* __restrict__ node,
                                                const float* __restrict__ hid,
                                                const float* __restrict__ Wm, const float* __restrict__ bm,
                                                const float* __restrict__ Wsk, const float* __restrict__ bsk,
                                                const float* __restrict__ W1, const float* __restrict__ b1,
                                                const float* __restrict__ W2, const float* __restrict__ b2) {
    __shared__ float Ws[32 * 132];
    __shared__ float zs[16 * 33];
    int by = blockIdx.y;
    const float* W    = by == 0 ? Wm : by == 1 ? Wsk : by == 2 ? W1 : W2;
    const float* bias = by == 0 ? bm : by == 1 ? bsk : by == 2 ? b1 : b2;

    int tid = threadIdx.x, lane = tid & 31, warp = tid >> 5;
    int j0 = blockIdx.x * 16;
    float acc[2][4] = {};
    for (int kc = 0; kc < 8; kc++) {
        int kb = kc * 32;
        __syncthreads();
        for (int e = tid; e < 4096; e += 256) {
            int kl = e >> 7, m = e & 127;
            Ws[kl * 132 + m] = W[(kb + kl) * 128 + m];
        }
        for (int e = tid; e < 512; e += 256) {
            int jl = e >> 5, kl = e & 31;
            int k = kb + kl;
            zs[jl * 33 + kl] = (k < 128) ? node[(j0 + jl) * 128 + k]
                                         : hid[(j0 + jl) * 128 + k - 128];
        }
        __syncthreads();
#pragma unroll 8
        for (int kl = 0; kl < 32; kl++) {
            float4 wv = *(const float4*)&Ws[kl * 132 + lane * 4];
#pragma unroll
            for (int r = 0; r < 2; r++) {
                float zv = zs[(warp * 2 + r) * 33 + kl];
                acc[r][0] += zv * wv.x; acc[r][1] += zv * wv.y;
                acc[r][2] += zv * wv.z; acc[r][3] += zv * wv.w;
            }
        }
    }
    float4 bv = *(const float4*)&bias[lane * 4];
    float4 gv = make_float4(0.f, 0.f, 0.f, 0.f);
    if (by == 3) gv = *(const float4*)&g_gterm[lane * 4];
    float* out = by == 0 ? g_vals : by == 1 ? g_skip : by == 2 ? g_pre1 : g_pre2g;
#pragma unroll
    for (int r = 0; r < 2; r++) {
        int j = j0 + warp * 2 + r;
        float4 o;
        o.x = acc[r][0] + bv.x + gv.x;
        o.y = acc[r][1] + bv.y + gv.y;
        o.z = acc[r][2] + bv.z + gv.z;
        o.w = acc[r][3] + bv.w + gv.w;
        *(float4*)&out[(size_t)j * 128 + lane * 4] = o;
    }
}

// ---------------- K2: persistent s8 IMMA m16n8k32, s32 accumulate ----------------
// Grid 296 (2/SM). Item = (i, jt): 128x128x128 tile + fused epilogue. 8192 items.
// 8 warps = 2(wm) x 4(wn), warp tile 64m x 32n. A ring: 3 buffers of 128x32 s8 (stride 12 words).
// B = We^T s8 (stride 36 words), staged once. One __syncthreads per chunk. 16 IMMA/warp/chunk.
__global__ __launch_bounds__(256, 2) void k2_logits(const float* __restrict__ edge,
                                                    const float* __restrict__ Aw,
                                                    const float* __restrict__ Abv,
                                                    const int* __restrict__ adj) {
    extern __shared__ unsigned shw[];
    unsigned* Abuf = shw;                 // 3 x 128*12 = 4608 words
    unsigned* Bsh = shw + 4608;           // 128*36 = 4608 words
    __shared__ float sAw[128], sAb[8];

    int tid = threadIdx.x, lane = tid & 31, warp = tid >> 5;
    int wm = warp >> 2, wn = warp & 3;
    int ro = lane >> 2, kq = lane & 3;

    int p = blockIdx.x;                    // 0..295
    int npi = 27 + (p < 200);
    int start = p * 27 + (p < 200 ? p : 200);
    int nchunks = npi * 4;

    float sAB = SA * g_sB;

    // stage B = We^T s8 once (16KB, STS.128, conflict-free)
    for (int e = tid; e < 1024; e += 256) {
        int n = e >> 3, seg = e & 7;
        uint4 v = *(const uint4*)(g_WeQ + n * 128 + seg * 16);
        *(uint4*)(Bsh + 36 * n + 4 * seg) = v;
    }
    if (tid < 128) sAw[tid] = Aw[tid];
    if (tid < 8)   sAb[tid] = Abv[tid];

    auto chunk_src = [&](int cidx) -> const float* {
        int item = start + (cidx >> 2);
        int i = item >> 3, jt = item & 7, kc = cidx & 3;
        return edge + (size_t)i * 131072 + (size_t)(jt * 128) * 128 + kc * 32;
    };
    auto ldg_chunk = [&](int cidx, float4* r) {
        const float* src = chunk_src(cidx);
#pragma unroll
        for (int it = 0; it < 4; it++) {
            int idx = it * 256 + tid;
            r[it] = __ldg((const float4*)(src + (idx >> 3) * 128 + (idx & 7) * 4));
        }
    };
    auto sts_chunk = [&](const float4* r, unsigned* dst) {
#pragma unroll
        for (int it = 0; it < 4; it++) {
            int idx = it * 256 + tid;
            int row = idx >> 3, q = idx & 7;
            dst[12 * row + q] = quant4(r[it], INV_SA);
        }
    };

    // prologue: chunk 0 staged, chunk 1 in registers
    float4 rg[4];
    ldg_chunk(0, rg);
    sts_chunk(rg, Abuf);
    ldg_chunk(1, rg);
    __syncthreads();

    int acc[4][4][4];
#pragma unroll
    for (int mi = 0; mi < 4; mi++)
#pragma unroll
        for (int ni = 0; ni < 4; ni++)
#pragma unroll
            for (int r = 0; r < 4; r++) acc[mi][ni][r] = 0;

    for (int cidx = 0; cidx < nchunks; cidx++) {
        const unsigned* Ab = Abuf + (cidx % 3) * 1536;
        int kc = cidx & 3;

        // IMMA phase: K=32 in one instruction per (mi, ni)
        unsigned b[4][2];
#pragma unroll
        for (int ni = 0; ni < 4; ni++) {
            const unsigned* bp = Bsh + 36 * (wn * 32 + ni * 8 + ro) + 8 * kc + kq;
            b[ni][0] = bp[0];
            b[ni][1] = bp[4];
        }
#pragma unroll
        for (int mi = 0; mi < 4; mi++) {
            const unsigned* ap = Ab + 12 * (wm * 64 + mi * 16 + ro) + kq;
            unsigned a0 = ap[0];
            unsigned a1 = ap[96];      // row +8
            unsigned a2 = ap[4];       // k +16
            unsigned a3 = ap[100];
#pragma unroll
            for (int ni = 0; ni < 4; ni++)
                asm volatile(
                    "mma.sync.aligned.m16n8k32.row.col.s32.s8.s8.s32 "
                    "{%0,%1,%2,%3}, {%4,%5,%6,%7}, {%8,%9}, {%0,%1,%2,%3};"
                    : "+r"(acc[mi][ni][0]), "+r"(acc[mi][ni][1]),
                      "+r"(acc[mi][ni][2]), "+r"(acc[mi][ni][3])
                    : "r"(a0), "r"(a1), "r"(a2), "r"(a3),
                      "r"(b[ni][0]), "r"(b[ni][1]));
        }

        if (kc == 3) {
            // epilogue for finished item
            int item = start + (cidx >> 2);
            int i = item >> 3, j0 = (item & 7) * 128;

            float p2x[4], p2y[4];
#pragma unroll
            for (int ni = 0; ni < 4; ni++) {
                int cb = wn * 32 + ni * 8 + kq * 2;
                float2 pv = __ldg((const float2*)&g_pre2g[i * 128 + cb]);
                p2x[ni] = pv.x; p2y[ni] = pv.y;
            }
            float hsum[4][2][2];
#pragma unroll
            for (int mi = 0; mi < 4; mi++)
#pragma unroll
                for (int rr = 0; rr < 2; rr++) {
                    hsum[mi][rr][0] = 0.f; hsum[mi][rr][1] = 0.f;
                }
#pragma unroll
            for (int mi = 0; mi < 4; mi++) {
#pragma unroll
                for (int rr = 0; rr < 2; rr++) {
                    int jrow = j0 + wm * 64 + mi * 16 + ro + rr * 8;
                    const float* p1 = g_pre1 + (size_t)jrow * 128;
#pragma unroll
                    for (int ni = 0; ni < 4; ni++) {
                        int cb = wn * 32 + ni * 8 + kq * 2;
                        float2 pv = __ldg((const float2*)&p1[cb]);
                        float x0 = (float)acc[mi][ni][rr * 2 + 0] * sAB + pv.x + p2x[ni];
                        float x1 = (float)acc[mi][ni][rr * 2 + 1] * sAB + pv.y + p2y[ni];
                        x0 = fmaxf(x0, 0.01f * x0);
                        x1 = fmaxf(x1, 0.01f * x1);
                        hsum[mi][rr][ni >> 1] += sAw[cb] * x0 + sAw[cb + 1] * x1;
                    }
                }
            }
#pragma unroll
            for (int off = 1; off <= 2; off <<= 1)
#pragma unroll
                for (int mi = 0; mi < 4; mi++)
#pragma unroll
                    for (int rr = 0; rr < 2; rr++) {
                        hsum[mi][rr][0] += __shfl_xor_sync(0xffffffffu, hsum[mi][rr][0], off);
                        hsum[mi][rr][1] += __shfl_xor_sync(0xffffffffu, hsum[mi][rr][1], off);
                    }
            int q = lane & 3;
            if (q < 2) {
                int h = wn * 2 + q;
                float ab = sAb[h];
#pragma unroll
                for (int mi = 0; mi < 4; mi++)
#pragma unroll
                    for (int rr = 0; rr < 2; rr++) {
                        int j = j0 + wm * 64 + mi * 16 + ro + rr * 8;
                        float lg = hsum[mi][rr][q] + ab
                                 + (__ldg(&adj[i * 1024 + j]) ? 0.f : -1e9f);
                        g_logits[((size_t)i * 8 + h) * 1024 + j] = lg;
                    }
            }
#pragma unroll
            for (int mi = 0; mi < 4; mi++)
#pragma unroll
                for (int ni = 0; ni < 4; ni++)
#pragma unroll
                    for (int r = 0; r < 4; r++) acc[mi][ni][r] = 0;
        }

        // stage chunk cidx+1 (in regs) into ring slot, then LDG cidx+2
        if (cidx + 1 < nchunks) sts_chunk(rg, Abuf + ((cidx + 1) % 3) * 1536);
        if (cidx + 2 < nchunks) ldg_chunk(cidx + 2, rg);
        __syncthreads();
    }
}

// ---------------- K3a: softmax -> normalized fp16 probs ----------------
__global__ __launch_bounds__(256) void k3a_softmax() {
    int i = blockIdx.x;
    int tid = threadIdx.x, lane = tid & 31, h = tid >> 5;
    const float* lg = g_logits + ((size_t)(i * 8 + h)) * 1024;

    float4 v[8];
#pragma unroll
    for (int t = 0; t < 8; t++) v[t] = ((const float4*)lg)[t * 32 + lane];
    float mx = -3.402823e38f;
#pragma unroll
    for (int t = 0; t < 8; t++)
        mx = fmaxf(mx, fmaxf(fmaxf(v[t].x, v[t].y), fmaxf(v[t].z, v[t].w)));
#pragma unroll
    for (int off = 16; off >= 1; off >>= 1)
        mx = fmaxf(mx, __shfl_xor_sync(0xffffffffu, mx, off));
    float ssum = 0.f;
#pragma unroll
    for (int t = 0; t < 8; t++) {
        v[t].x = __expf(v[t].x - mx); v[t].y = __expf(v[t].y - mx);
        v[t].z = __expf(v[t].z - mx); v[t].w = __expf(v[t].w - mx);
        ssum += v[t].x + v[t].y + v[t].z + v[t].w;
    }
#pragma unroll
    for (int off = 16; off >= 1; off >>= 1)
        ssum += __shfl_xor_sync(0xffffffffu, ssum, off);
    float inv = 1.f / ssum;

    __half* pr = g_probs + ((size_t)(i * 8 + h)) * 1024;
#pragma unroll
    for (int t = 0; t < 8; t++) {
        __half2 ha = __floats2half2_rn(v[t].x * inv, v[t].y * inv);
        __half2 hb = __floats2half2_rn(v[t].z * inv, v[t].w * inv);
        *(uint2*)&pr[(t * 32 + lane) * 4] = make_uint2(h2u(ha), h2u(hb));
    }
}

// ---------------- K3b: AV + skip + relu ----------------
__global__ __launch_bounds__(256) void k3b_av(float* __restrict__ out) {
    extern __shared__ float s3[];
    float* Vs = s3;                                  // 1024*17 floats
    __half* Ps = (__half*)(s3 + 1024 * 17);          // 32*132 halfs
    uint2* Psu = (uint2*)Ps;

    int i0 = blockIdx.x * 32, h = blockIdx.y;
    int tid = threadIdx.x;
    int il = tid >> 3, c0 = tid & 7;

    for (int e = tid; e < 16384; e += 256) {
        int j = e >> 4, cc = e & 15;
        Vs[j * 17 + cc] = g_vals[(size_t)j * 128 + h * 16 + cc];
    }

    float acc0 = 0.f, acc1 = 0.f;
    for (int jt = 0; jt < 8; jt++) {
        __syncthreads();
        for (int e = tid; e < 1024; e += 256) {
            int r = e >> 5, q = e & 31;
            const __half* src = g_probs + ((size_t)(i0 + r) * 8 + h) * 1024 + jt * 128;
            Psu[r * 33 + q] = *(const uint2*)(src + q * 4);
        }
        __syncthreads();
        const __half2* prow = (const __half2*)(Ps + il * 132);
        const float* vbase = Vs + (jt * 128) * 17;
#pragma unroll 8
        for (int jj2 = 0; jj2 < 64; jj2++) {
            float2 pf = __half22float2(prow[jj2]);
            const float* v0 = vbase + (2 * jj2) * 17;
            acc0 += pf.x * v0[c0]      + pf.y * v0[17 + c0];
            acc1 += pf.x * v0[c0 + 8]  + pf.y * v0[17 + c0 + 8];
        }
    }
    int o = (i0 + il) * 128 + h * 16 + c0;
    out[o]     = fmaxf(acc0 + g_skip[o], 0.f);
    out[o + 8] = fmaxf(acc1 + g_skip[o + 8], 0.f);
}

// ---------------- launch ----------------
extern "C" void kernel_launch(void* const* d_in, const int* in_sizes, int n_in,
                              void* d_out, int out_size) {
    const float* node   = (const float*)d_in[0];
    const float* edge   = (const float*)d_in[1];
    const float* graph  = (const float*)d_in[2];
    const int*   adj    = (const int*)  d_in[3];
    const float* hidden = (const float*)d_in[4];
    const float* Wm     = (const float*)d_in[5];
    const float* bm     = (const float*)d_in[6];
    const float* Wskip  = (const float*)d_in[7];
    const float* bskip  = (const float*)d_in[8];
    const float* W1     = (const float*)d_in[9];
    const float* b1     = (const float*)d_in[10];
    const float* W2     = (const float*)d_in[11];
    const float* b2     = (const float*)d_in[12];
    const float* We     = (const float*)d_in[13];
    const float* be     = (const float*)d_in[14];
    const float* Wg     = (const float*)d_in[15];
    const float* bg     = (const float*)d_in[16];
    const float* Aw     = (const float*)d_in[17];
    const float* Abv    = (const float*)d_in[18];
    float* out = (float*)d_out;

    k0_gterm<<<1, 128>>>(graph, Wg, bg, be);
    k_quantWe<<<1, 256>>>(We);
    k1_fused<<<dim3(64, 4), 256>>>(node, hidden, Wm, bm, Wskip, bskip, W1, b1, W2, b2);

    const int smem2 = (4608 + 4608) * sizeof(unsigned);   // 36,864 B
    cudaFuncSetAttribute(k2_logits, cudaFuncAttributeMaxDynamicSharedMemorySize, smem2);
    k2_logits<<<296, 256, smem2>>>(edge, Aw, Abv, adj);

    k3a_softmax<<<1024, 256>>>();

    const int smem3 = 1024 * 17 * sizeof(float) + 32 * 132 * sizeof(__half);    // 78,080 B
    cudaFuncSetAttribute(k3b_av, cudaFuncAttributeMaxDynamicSharedMemorySize, smem3);
    k3b_av<<<dim3(32, 8), 256, smem3>>>(out);
}

// round 16
// speedup vs baseline: 1.5504x; 1.5504x over previous
#include <cuda_runtime.h>
#include <cuda_fp16.h>
#include <cstdint>

#define NN 1024

// ---------------- scratch (device globals; no allocs) ----------------
__device__ float g_pre1[NN * 128];        // [j][m]
__device__ float g_pre2g[NN * 128];
__device__ float g_vals[NN * 128];        // [j][c]
__device__ float g_skip[NN * 128];
__device__ float g_logits[(size_t)8 * NN * NN];   // [i][h][j]
__device__ __half g_probs[(size_t)8 * NN * NN];   // normalized softmax probs, fp16

// ---------------- helpers ----------------
__device__ __forceinline__ unsigned h2u(__half2 h) { return *(unsigned*)&h; }

// ---------------- K1 (fused: 4 projections + inline graph term) ----------------
// grid (64, 4). by==3 computes gterm = graph@Wg + bg + be locally (tiny), adds to pre2.
__global__ __launch_bounds__(256) void k1_fused(const float* __restrict__ node,
                                                const float* __restrict__ hid,
                                                const float* __restrict__ gf,
                                                const float* __restrict__ Wg,
                                                const float* __restrict__ bgv,
                                                const float* __restrict__ bev,
                                                const float* __restrict__ Wm, const float* __restrict__ bm,
                                                const float* __restrict__ Wsk, const float* __restrict__ bsk,
                                                const float* __restrict__ W1, const float* __restrict__ b1,
                                                const float* __restrict__ W2, const float* __restrict__ b2) {
    __shared__ float Ws[32 * 132];
    __shared__ float zs[16 * 33];
    __shared__ float sgt[128];
    int by = blockIdx.y;
    const float* W    = by == 0 ? Wm : by == 1 ? Wsk : by == 2 ? W1 : W2;
    const float* bias = by == 0 ? bm : by == 1 ? bsk : by == 2 ? b1 : b2;

    int tid = threadIdx.x, lane = tid & 31, warp = tid >> 5;
    int j0 = blockIdx.x * 16;

    if (by == 3) {                    // CTA-local graph term (uniform branch)
        if (tid < 128) {
            float a = bgv[tid] + bev[tid];
#pragma unroll 8
            for (int k = 0; k < 128; k++) a += gf[k] * Wg[k * 128 + tid];
            sgt[tid] = a;
        }
        __syncthreads();
    }

    float acc[2][4] = {};
    for (int kc = 0; kc < 8; kc++) {
        int kb = kc * 32;
        __syncthreads();
        for (int e = tid; e < 4096; e += 256) {
            int kl = e >> 7, m = e & 127;
            Ws[kl * 132 + m] = W[(kb + kl) * 128 + m];
        }
        for (int e = tid; e < 512; e += 256) {
            int jl = e >> 5, kl = e & 31;
            int k = kb + kl;
            zs[jl * 33 + kl] = (k < 128) ? node[(j0 + jl) * 128 + k]
                                         : hid[(j0 + jl) * 128 + k - 128];
        }
        __syncthreads();
#pragma unroll 8
        for (int kl = 0; kl < 32; kl++) {
            float4 wv = *(const float4*)&Ws[kl * 132 + lane * 4];
#pragma unroll
            for (int r = 0; r < 2; r++) {
                float zv = zs[(warp * 2 + r) * 33 + kl];
                acc[r][0] += zv * wv.x; acc[r][1] += zv * wv.y;
                acc[r][2] += zv * wv.z; acc[r][3] += zv * wv.w;
            }
        }
    }
    float4 bv = *(const float4*)&bias[lane * 4];
    float4 gv = make_float4(0.f, 0.f, 0.f, 0.f);
    if (by == 3) gv = *(const float4*)&sgt[lane * 4];
    float* out = by == 0 ? g_vals : by == 1 ? g_skip : by == 2 ? g_pre1 : g_pre2g;
#pragma unroll
    for (int r = 0; r < 2; r++) {
        int j = j0 + warp * 2 + r;
        float4 o;
        o.x = acc[r][0] + bv.x + gv.x;
        o.y = acc[r][1] + bv.y + gv.y;
        o.z = acc[r][2] + bv.z + gv.z;
        o.w = acc[r][3] + bv.w + gv.w;
        *(float4*)&out[(size_t)j * 128 + lane * 4] = o;
    }
}

// ---------------- K2: persistent fp16 m16n8k16, fp16 accumulators (R14, at HW ceiling) ----------------
// Grid 296 (2/SM). Item = (i, jt): 128x128x128 tile + fused epilogue. 8192 items.
// 8 warps = 2(wm) x 4(wn), warp tile 64m x 32n. A ring: 3 buffers of 128x32 fp16 (stride 40).
// B = We^T fp16 (stride 136), staged once. One __syncthreads per chunk.
__global__ __launch_bounds__(256, 2) void k2_logits(const float* __restrict__ edge,
                                                    const float* __restrict__ We,
                                                    const float* __restrict__ Aw,
                                                    const float* __restrict__ Abv,
                                                    const int* __restrict__ adj) {
    extern __shared__ __half sh[];
    __half* Abuf = sh;                            // 3 x 5120 halfs
    __half* Bsh = sh + 15360;                     // 128*136 halfs
    __shared__ float sAw[128], sAb[8];

    int tid = threadIdx.x, lane = tid & 31, warp = tid >> 5;
    int wm = warp >> 2, wn = warp & 3;
    int ro = lane >> 2, kq = lane & 3;

    int p = blockIdx.x;                            // 0..295
    int npi = 27 + (p < 200);
    int start = p * 27 + (p < 200 ? p : 200);
    int nchunks = npi * 4;

    // stage B = We^T fp16 once
    for (int e = tid; e < 16384; e += 256) {
        int k = e >> 7, m = e & 127;
        Bsh[m * 136 + k] = __float2half_rn(We[k * 128 + m]);
    }
    if (tid < 128) sAw[tid] = Aw[tid];
    if (tid < 8)   sAb[tid] = Abv[tid];

    auto chunk_src = [&](int cidx) -> const float* {
        int item = start + (cidx >> 2);
        int i = item >> 3, jt = item & 7, kc = cidx & 3;
        return edge + (size_t)i * 131072 + (size_t)(jt * 128) * 128 + kc * 32;
    };
    auto ldg_chunk = [&](int cidx, float4* r) {
        const float* src = chunk_src(cidx);
#pragma unroll
        for (int it = 0; it < 4; it++) {
            int idx = it * 256 + tid;
            r[it] = __ldg((const float4*)(src + (idx >> 3) * 128 + (idx & 7) * 4));
        }
    };
    auto sts_chunk = [&](const float4* r, __half* dst) {
#pragma unroll
        for (int it = 0; it < 4; it++) {
            int idx = it * 256 + tid;
            int row = idx >> 3, q = idx & 7;
            __half2 h0 = __floats2half2_rn(r[it].x, r[it].y);
            __half2 h1 = __floats2half2_rn(r[it].z, r[it].w);
            *(uint2*)(dst + row * 40 + q * 4) = make_uint2(h2u(h0), h2u(h1));
        }
    };

    // prologue: chunk 0 staged, chunk 1 in registers
    float4 rg[4];
    ldg_chunk(0, rg);
    sts_chunk(rg, Abuf);
    ldg_chunk(1, rg);
    __syncthreads();

    unsigned acc[4][4][2];        // half2 accumulators: [mi][ni][rr]
#pragma unroll
    for (int mi = 0; mi < 4; mi++)
#pragma unroll
        for (int ni = 0; ni < 4; ni++) { acc[mi][ni][0] = 0u; acc[mi][ni][1] = 0u; }

    for (int cidx = 0; cidx < nchunks; cidx++) {
        const __half* Ab = Abuf + (cidx % 3) * 5120;
        int kc = cidx & 3;

        // MMA phase (fp16 D/C)
#pragma unroll
        for (int ks = 0; ks < 2; ks++) {
            int kf = ks * 16 + 2 * kq;
            int kg = kc * 32 + kf;
            unsigned b[4][2];
#pragma unroll
            for (int ni = 0; ni < 4; ni++) {
                const __half* bp = Bsh + (wn * 32 + ni * 8 + ro) * 136 + kg;
                b[ni][0] = *(const unsigned*)bp;
                b[ni][1] = *(const unsigned*)(bp + 8);
            }
#pragma unroll
            for (int mi = 0; mi < 4; mi++) {
                int r0 = (wm * 64 + mi * 16 + ro) * 40 + kf;
                unsigned a0 = *(const unsigned*)(Ab + r0);
                unsigned a1 = *(const unsigned*)(Ab + r0 + 320);
                unsigned a2 = *(const unsigned*)(Ab + r0 + 8);
                unsigned a3 = *(const unsigned*)(Ab + r0 + 328);
#pragma unroll
                for (int ni = 0; ni < 4; ni++)
                    asm volatile(
                        "mma.sync.aligned.m16n8k16.row.col.f16.f16.f16.f16 "
                        "{%0,%1}, {%2,%3,%4,%5}, {%6,%7}, {%0,%1};"
                        : "+r"(acc[mi][ni][0]), "+r"(acc[mi][ni][1])
                        : "r"(a0), "r"(a1), "r"(a2), "r"(a3),
                          "r"(b[ni][0]), "r"(b[ni][1]));
            }
        }

        if (kc == 3) {
            // epilogue for finished item
            int item = start + (cidx >> 2);
            int i = item >> 3, j0 = (item & 7) * 128;

            float p2x[4], p2y[4];
#pragma unroll
            for (int ni = 0; ni < 4; ni++) {
                int cb = wn * 32 + ni * 8 + kq * 2;
                float2 pv = __ldg((const float2*)&g_pre2g[i * 128 + cb]);
                p2x[ni] = pv.x; p2y[ni] = pv.y;
            }
            float hsum[4][2][2];
#pragma unroll
            for (int mi = 0; mi < 4; mi++)
#pragma unroll
                for (int rr = 0; rr < 2; rr++) {
                    hsum[mi][rr][0] = 0.f; hsum[mi][rr][1] = 0.f;
                }
#pragma unroll
            for (int mi = 0; mi < 4; mi++) {
#pragma unroll
                for (int rr = 0; rr < 2; rr++) {
                    int jrow = j0 + wm * 64 + mi * 16 + ro + rr * 8;
                    const float* p1 = g_pre1 + (size_t)jrow * 128;
                    float2 pv[4];
#pragma unroll
                    for (int ni = 0; ni < 4; ni++) {
                        int cb = wn * 32 + ni * 8 + kq * 2;
                        pv[ni] = __ldg((const float2*)&p1[cb]);
                    }
#pragma unroll
                    for (int ni = 0; ni < 4; ni++) {
                        int cb = wn * 32 + ni * 8 + kq * 2;
                        float2 cf = __half22float2(*(__half2*)&acc[mi][ni][rr]);
                        float x0 = cf.x + pv[ni].x + p2x[ni];
                        float x1 = cf.y + pv[ni].y + p2y[ni];
                        x0 = fmaxf(x0, 0.01f * x0);
                        x1 = fmaxf(x1, 0.01f * x1);
                        hsum[mi][rr][ni >> 1] += sAw[cb] * x0 + sAw[cb + 1] * x1;
                    }
                }
            }
#pragma unroll
            for (int off = 1; off <= 2; off <<= 1)
#pragma unroll
                for (int mi = 0; mi < 4; mi++)
#pragma unroll
                    for (int rr = 0; rr < 2; rr++) {
                        hsum[mi][rr][0] += __shfl_xor_sync(0xffffffffu, hsum[mi][rr][0], off);
                        hsum[mi][rr][1] += __shfl_xor_sync(0xffffffffu, hsum[mi][rr][1], off);
                    }
            int q = lane & 3;
            if (q < 2) {
                int h = wn * 2 + q;
                float ab = sAb[h];
#pragma unroll
                for (int mi = 0; mi < 4; mi++)
#pragma unroll
                    for (int rr = 0; rr < 2; rr++) {
                        int j = j0 + wm * 64 + mi * 16 + ro + rr * 8;
                        float lg = hsum[mi][rr][q] + ab
                                 + (__ldg(&adj[i * 1024 + j]) ? 0.f : -1e9f);
                        g_logits[((size_t)i * 8 + h) * 1024 + j] = lg;
                    }
            }
#pragma unroll
            for (int mi = 0; mi < 4; mi++)
#pragma unroll
                for (int ni = 0; ni < 4; ni++) { acc[mi][ni][0] = 0u; acc[mi][ni][1] = 0u; }
        }

        // stage chunk cidx+1 (data already in regs) into ring slot, then LDG cidx+2
        if (cidx + 1 < nchunks) sts_chunk(rg, Abuf + ((cidx + 1) % 3) * 5120);
        if (cidx + 2 < nchunks) ldg_chunk(cidx + 2, rg);
        __syncthreads();
    }
}

// ---------------- K3a: softmax -> normalized fp16 probs ----------------
__global__ __launch_bounds__(256) void k3a_softmax() {
    int i = blockIdx.x;
    int tid = threadIdx.x, lane = tid & 31, h = tid >> 5;
    const float* lg = g_logits + ((size_t)(i * 8 + h)) * 1024;

    float4 v[8];
#pragma unroll
    for (int t = 0; t < 8; t++) v[t] = ((const float4*)lg)[t * 32 + lane];
    float mx = -3.402823e38f;
#pragma unroll
    for (int t = 0; t < 8; t++)
        mx = fmaxf(mx, fmaxf(fmaxf(v[t].x, v[t].y), fmaxf(v[t].z, v[t].w)));
#pragma unroll
    for (int off = 16; off >= 1; off >>= 1)
        mx = fmaxf(mx, __shfl_xor_sync(0xffffffffu, mx, off));
    float ssum = 0.f;
#pragma unroll
    for (int t = 0; t < 8; t++) {
        v[t].x = __expf(v[t].x - mx); v[t].y = __expf(v[t].y - mx);
        v[t].z = __expf(v[t].z - mx); v[t].w = __expf(v[t].w - mx);
        ssum += v[t].x + v[t].y + v[t].z + v[t].w;
    }
#pragma unroll
    for (int off = 16; off >= 1; off >>= 1)
        ssum += __shfl_xor_sync(0xffffffffu, ssum, off);
    float inv = 1.f / ssum;

    __half* pr = g_probs + ((size_t)(i * 8 + h)) * 1024;
#pragma unroll
    for (int t = 0; t < 8; t++) {
        __half2 ha = __floats2half2_rn(v[t].x * inv, v[t].y * inv);
        __half2 hb = __floats2half2_rn(v[t].z * inv, v[t].w * inv);
        *(uint2*)&pr[(t * 32 + lane) * 4] = make_uint2(h2u(ha), h2u(hb));
    }
}

// ---------------- K3b: AV + skip + relu (LDS.64 value loads, stride-18 V) ----------------
// grid (32, 8): CTA = 32 i-rows x head h. Thread owns cols (2c0, 2c0+1) of the head.
__global__ __launch_bounds__(256) void k3b_av(float* __restrict__ out) {
    extern __shared__ float s3[];
    float* Vs = s3;                                  // 1024*18 floats = 73728 B
    __half* Ps = (__half*)(s3 + 1024 * 18);          // 32*132 halfs = 8448 B
    uint2* Psu = (uint2*)Ps;

    int i0 = blockIdx.x * 32, h = blockIdx.y;
    int tid = threadIdx.x;
    int il = tid >> 3, c0 = tid & 7;

    // stage V_h: Vs[j][c] = g_vals[j*128 + h*16 + c], row stride 18 (even -> float2 reads)
    for (int e = tid; e < 16384; e += 256) {
        int j = e >> 4, cc = e & 15;
        Vs[j * 18 + cc] = g_vals[(size_t)j * 128 + h * 16 + cc];
    }

    float acc0 = 0.f, acc1 = 0.f;
    for (int jt = 0; jt < 8; jt++) {
        __syncthreads();
        for (int e = tid; e < 1024; e += 256) {
            int r = e >> 5, q = e & 31;
            const __half* src = g_probs + ((size_t)(i0 + r) * 8 + h) * 1024 + jt * 128;
            Psu[r * 33 + q] = *(const uint2*)(src + q * 4);
        }
        __syncthreads();
        const __half2* prow = (const __half2*)(Ps + il * 132);
        const float* vbase = Vs + (jt * 128) * 18;
#pragma unroll 8
        for (int jj2 = 0; jj2 < 64; jj2++) {
            float2 pf = __half22float2(prow[jj2]);
            float2 va = *(const float2*)&vbase[36 * jj2 + 2 * c0];
            float2 vb = *(const float2*)&vbase[36 * jj2 + 18 + 2 * c0];
            acc0 += pf.x * va.x + pf.y * vb.x;
            acc1 += pf.x * va.y + pf.y * vb.y;
        }
    }
    int o = (i0 + il) * 128 + h * 16 + 2 * c0;
    out[o]     = fmaxf(acc0 + g_skip[o], 0.f);
    out[o + 1] = fmaxf(acc1 + g_skip[o + 1], 0.f);
}

// ---------------- launch ----------------
extern "C" void kernel_launch(void* const* d_in, const int* in_sizes, int n_in,
                              void* d_out, int out_size) {
    const float* node   = (const float*)d_in[0];
    const float* edge   = (const float*)d_in[1];
    const float* graph  = (const float*)d_in[2];
    const int*   adj    = (const int*)  d_in[3];
    const float* hidden = (const float*)d_in[4];
    const float* Wm     = (const float*)d_in[5];
    const float* bm     = (const float*)d_in[6];
    const float* Wskip  = (const float*)d_in[7];
    const float* bskip  = (const float*)d_in[8];
    const float* W1     = (const float*)d_in[9];
    const float* b1     = (const float*)d_in[10];
    const float* W2     = (const float*)d_in[11];
    const float* b2     = (const float*)d_in[12];
    const float* We     = (const float*)d_in[13];
    const float* be     = (const float*)d_in[14];
    const float* Wg     = (const float*)d_in[15];
    const float* bg     = (const float*)d_in[16];
    const float* Aw     = (const float*)d_in[17];
    const float* Abv    = (const float*)d_in[18];
    float* out = (float*)d_out;

    k1_fused<<<dim3(64, 4), 256>>>(node, hidden, graph, Wg, bg, be,
                                   Wm, bm, Wskip, bskip, W1, b1, W2, b2);

    const int smem2 = (3 * 5120 + 128 * 136) * sizeof(__half);   // 65,536 B
    cudaFuncSetAttribute(k2_logits, cudaFuncAttributeMaxDynamicSharedMemorySize, smem2);
    k2_logits<<<296, 256, smem2>>>(edge, We, Aw, Abv, adj);

    k3a_softmax<<<1024, 256>>>();

    const int smem3 = 1024 * 18 * sizeof(float) + 32 * 132 * sizeof(__half);    // 82,176 B
    cudaFuncSetAttribute(k3b_av, cudaFuncAttributeMaxDynamicSharedMemorySize, smem3);
    k3b_av<<<dim3(32, 8), 256, smem3>>>(out);
}

// round 17
// speedup vs baseline: 1.7116x; 1.1039x over previous
#include <cuda_runtime.h>
#include <cuda_fp16.h>
#include <cstdint>

#define NN 1024

// ---------------- scratch (device globals; no allocs) ----------------
__device__ float g_pre1[NN * 128];        // [j][m]
__device__ float g_pre2g[NN * 128];
__device__ float g_vals[NN * 128];        // [j][c]
__device__ float g_skip[NN * 128];
__device__ float g_logits[(size_t)8 * NN * NN];   // [i][h][j]
__device__ __half g_probs[(size_t)8 * NN * NN];   // normalized softmax probs, fp16

// ---------------- helpers ----------------
__device__ __forceinline__ unsigned h2u(__half2 h) { return *(unsigned*)&h; }
__device__ __forceinline__ void cp16h(__half* dst, const __half* src) {
    unsigned s = (unsigned)__cvta_generic_to_shared(dst);
    asm volatile("cp.async.cg.shared.global [%0], [%1], 16;" :: "r"(s), "l"(src));
}
__device__ __forceinline__ void cp_commit() { asm volatile("cp.async.commit_group;"); }
__device__ __forceinline__ void cp_wait0() { asm volatile("cp.async.wait_group 0;"); }
__device__ __forceinline__ void cp_wait1() { asm volatile("cp.async.wait_group 1;"); }

// ---------------- K1 (fused: 4 projections + inline graph term) ----------------
__global__ __launch_bounds__(256) void k1_fused(const float* __restrict__ node,
                                                const float* __restrict__ hid,
                                                const float* __restrict__ gf,
                                                const float* __restrict__ Wg,
                                                const float* __restrict__ bgv,
                                                const float* __restrict__ bev,
                                                const float* __restrict__ Wm, const float* __restrict__ bm,
                                                const float* __restrict__ Wsk, const float* __restrict__ bsk,
                                                const float* __restrict__ W1, const float* __restrict__ b1,
                                                const float* __restrict__ W2, const float* __restrict__ b2) {
    __shared__ float Ws[32 * 132];
    __shared__ float zs[16 * 33];
    __shared__ float sgt[128];
    int by = blockIdx.y;
    const float* W    = by == 0 ? Wm : by == 1 ? Wsk : by == 2 ? W1 : W2;
    const float* bias = by == 0 ? bm : by == 1 ? bsk : by == 2 ? b1 : b2;

    int tid = threadIdx.x, lane = tid & 31, warp = tid >> 5;
    int j0 = blockIdx.x * 16;

    if (by == 3) {
        if (tid < 128) {
            float a = bgv[tid] + bev[tid];
#pragma unroll 8
            for (int k = 0; k < 128; k++) a += gf[k] * Wg[k * 128 + tid];
            sgt[tid] = a;
        }
        __syncthreads();
    }

    float acc[2][4] = {};
    for (int kc = 0; kc < 8; kc++) {
        int kb = kc * 32;
        __syncthreads();
        for (int e = tid; e < 4096; e += 256) {
            int kl = e >> 7, m = e & 127;
            Ws[kl * 132 + m] = W[(kb + kl) * 128 + m];
        }
        for (int e = tid; e < 512; e += 256) {
            int jl = e >> 5, kl = e & 31;
            int k = kb + kl;
            zs[jl * 33 + kl] = (k < 128) ? node[(j0 + jl) * 128 + k]
                                         : hid[(j0 + jl) * 128 + k - 128];
        }
        __syncthreads();
#pragma unroll 8
        for (int kl = 0; kl < 32; kl++) {
            float4 wv = *(const float4*)&Ws[kl * 132 + lane * 4];
#pragma unroll
            for (int r = 0; r < 2; r++) {
                float zv = zs[(warp * 2 + r) * 33 + kl];
                acc[r][0] += zv * wv.x; acc[r][1] += zv * wv.y;
                acc[r][2] += zv * wv.z; acc[r][3] += zv * wv.w;
            }
        }
    }
    float4 bv = *(const float4*)&bias[lane * 4];
    float4 gv = make_float4(0.f, 0.f, 0.f, 0.f);
    if (by == 3) gv = *(const float4*)&sgt[lane * 4];
    float* out = by == 0 ? g_vals : by == 1 ? g_skip : by == 2 ? g_pre1 : g_pre2g;
#pragma unroll
    for (int r = 0; r < 2; r++) {
        int j = j0 + warp * 2 + r;
        float4 o;
        o.x = acc[r][0] + bv.x + gv.x;
        o.y = acc[r][1] + bv.y + gv.y;
        o.z = acc[r][2] + bv.z + gv.z;
        o.w = acc[r][3] + bv.w + gv.w;
        *(float4*)&out[(size_t)j * 128 + lane * 4] = o;
    }
}

// ---------------- K2: persistent fp16 m16n8k16, fp16 accumulators (at legacy-HMMA ceiling) ----------------
__global__ __launch_bounds__(256, 2) void k2_logits(const float* __restrict__ edge,
                                                    const float* __restrict__ We,
                                                    const float* __restrict__ Aw,
                                                    const float* __restrict__ Abv,
                                                    const int* __restrict__ adj) {
    extern __shared__ __half sh[];
    __half* Abuf = sh;                            // 3 x 5120 halfs
    __half* Bsh = sh + 15360;                     // 128*136 halfs
    __shared__ float sAw[128], sAb[8];

    int tid = threadIdx.x, lane = tid & 31, warp = tid >> 5;
    int wm = warp >> 2, wn = warp & 3;
    int ro = lane >> 2, kq = lane & 3;

    int p = blockIdx.x;
    int npi = 27 + (p < 200);
    int start = p * 27 + (p < 200 ? p : 200);
    int nchunks = npi * 4;

    for (int e = tid; e < 16384; e += 256) {
        int k = e >> 7, m = e & 127;
        Bsh[m * 136 + k] = __float2half_rn(We[k * 128 + m]);
    }
    if (tid < 128) sAw[tid] = Aw[tid];
    if (tid < 8)   sAb[tid] = Abv[tid];

    auto chunk_src = [&](int cidx) -> const float* {
        int item = start + (cidx >> 2);
        int i = item >> 3, jt = item & 7, kc = cidx & 3;
        return edge + (size_t)i * 131072 + (size_t)(jt * 128) * 128 + kc * 32;
    };
    auto ldg_chunk = [&](int cidx, float4* r) {
        const float* src = chunk_src(cidx);
#pragma unroll
        for (int it = 0; it < 4; it++) {
            int idx = it * 256 + tid;
            r[it] = __ldg((const float4*)(src + (idx >> 3) * 128 + (idx & 7) * 4));
        }
    };
    auto sts_chunk = [&](const float4* r, __half* dst) {
#pragma unroll
        for (int it = 0; it < 4; it++) {
            int idx = it * 256 + tid;
            int row = idx >> 3, q = idx & 7;
            __half2 h0 = __floats2half2_rn(r[it].x, r[it].y);
            __half2 h1 = __floats2half2_rn(r[it].z, r[it].w);
            *(uint2*)(dst + row * 40 + q * 4) = make_uint2(h2u(h0), h2u(h1));
        }
    };

    float4 rg[4];
    ldg_chunk(0, rg);
    sts_chunk(rg, Abuf);
    ldg_chunk(1, rg);
    __syncthreads();

    unsigned acc[4][4][2];
#pragma unroll
    for (int mi = 0; mi < 4; mi++)
#pragma unroll
        for (int ni = 0; ni < 4; ni++) { acc[mi][ni][0] = 0u; acc[mi][ni][1] = 0u; }

    for (int cidx = 0; cidx < nchunks; cidx++) {
        const __half* Ab = Abuf + (cidx % 3) * 5120;
        int kc = cidx & 3;

#pragma unroll
        for (int ks = 0; ks < 2; ks++) {
            int kf = ks * 16 + 2 * kq;
            int kg = kc * 32 + kf;
            unsigned b[4][2];
#pragma unroll
            for (int ni = 0; ni < 4; ni++) {
                const __half* bp = Bsh + (wn * 32 + ni * 8 + ro) * 136 + kg;
                b[ni][0] = *(const unsigned*)bp;
                b[ni][1] = *(const unsigned*)(bp + 8);
            }
#pragma unroll
            for (int mi = 0; mi < 4; mi++) {
                int r0 = (wm * 64 + mi * 16 + ro) * 40 + kf;
                unsigned a0 = *(const unsigned*)(Ab + r0);
                unsigned a1 = *(const unsigned*)(Ab + r0 + 320);
                unsigned a2 = *(const unsigned*)(Ab + r0 + 8);
                unsigned a3 = *(const unsigned*)(Ab + r0 + 328);
#pragma unroll
                for (int ni = 0; ni < 4; ni++)
                    asm volatile(
                        "mma.sync.aligned.m16n8k16.row.col.f16.f16.f16.f16 "
                        "{%0,%1}, {%2,%3,%4,%5}, {%6,%7}, {%0,%1};"
                        : "+r"(acc[mi][ni][0]), "+r"(acc[mi][ni][1])
                        : "r"(a0), "r"(a1), "r"(a2), "r"(a3),
                          "r"(b[ni][0]), "r"(b[ni][1]));
            }
        }

        if (kc == 3) {
            int item = start + (cidx >> 2);
            int i = item >> 3, j0 = (item & 7) * 128;

            float p2x[4], p2y[4];
#pragma unroll
            for (int ni = 0; ni < 4; ni++) {
                int cb = wn * 32 + ni * 8 + kq * 2;
                float2 pv = __ldg((const float2*)&g_pre2g[i * 128 + cb]);
                p2x[ni] = pv.x; p2y[ni] = pv.y;
            }
            float hsum[4][2][2];
#pragma unroll
            for (int mi = 0; mi < 4; mi++)
#pragma unroll
                for (int rr = 0; rr < 2; rr++) {
                    hsum[mi][rr][0] = 0.f; hsum[mi][rr][1] = 0.f;
                }
#pragma unroll
            for (int mi = 0; mi < 4; mi++) {
#pragma unroll
                for (int rr = 0; rr < 2; rr++) {
                    int jrow = j0 + wm * 64 + mi * 16 + ro + rr * 8;
                    const float* p1 = g_pre1 + (size_t)jrow * 128;
                    float2 pv[4];
#pragma unroll
                    for (int ni = 0; ni < 4; ni++) {
                        int cb = wn * 32 + ni * 8 + kq * 2;
                        pv[ni] = __ldg((const float2*)&p1[cb]);
                    }
#pragma unroll
                    for (int ni = 0; ni < 4; ni++) {
                        int cb = wn * 32 + ni * 8 + kq * 2;
                        float2 cf = __half22float2(*(__half2*)&acc[mi][ni][rr]);
                        float x0 = cf.x + pv[ni].x + p2x[ni];
                        float x1 = cf.y + pv[ni].y + p2y[ni];
                        x0 = fmaxf(x0, 0.01f * x0);
                        x1 = fmaxf(x1, 0.01f * x1);
                        hsum[mi][rr][ni >> 1] += sAw[cb] * x0 + sAw[cb + 1] * x1;
                    }
                }
            }
#pragma unroll
            for (int off = 1; off <= 2; off <<= 1)
#pragma unroll
                for (int mi = 0; mi < 4; mi++)
#pragma unroll
                    for (int rr = 0; rr < 2; rr++) {
                        hsum[mi][rr][0] += __shfl_xor_sync(0xffffffffu, hsum[mi][rr][0], off);
                        hsum[mi][rr][1] += __shfl_xor_sync(0xffffffffu, hsum[mi][rr][1], off);
                    }
            int q = lane & 3;
            if (q < 2) {
                int h = wn * 2 + q;
                float ab = sAb[h];
#pragma unroll
                for (int mi = 0; mi < 4; mi++)
#pragma unroll
                    for (int rr = 0; rr < 2; rr++) {
                        int j = j0 + wm * 64 + mi * 16 + ro + rr * 8;
                        float lg = hsum[mi][rr][q] + ab
                                 + (__ldg(&adj[i * 1024 + j]) ? 0.f : -1e9f);
                        g_logits[((size_t)i * 8 + h) * 1024 + j] = lg;
                    }
            }
#pragma unroll
            for (int mi = 0; mi < 4; mi++)
#pragma unroll
                for (int ni = 0; ni < 4; ni++) { acc[mi][ni][0] = 0u; acc[mi][ni][1] = 0u; }
        }

        if (cidx + 1 < nchunks) sts_chunk(rg, Abuf + ((cidx + 1) % 3) * 5120);
        if (cidx + 2 < nchunks) ldg_chunk(cidx + 2, rg);
        __syncthreads();
    }
}

// ---------------- K3a: softmax -> normalized fp16 probs ----------------
__global__ __launch_bounds__(256) void k3a_softmax() {
    int i = blockIdx.x;
    int tid = threadIdx.x, lane = tid & 31, h = tid >> 5;
    const float* lg = g_logits + ((size_t)(i * 8 + h)) * 1024;

    float4 v[8];
#pragma unroll
    for (int t = 0; t < 8; t++) v[t] = ((const float4*)lg)[t * 32 + lane];
    float mx = -3.402823e38f;
#pragma unroll
    for (int t = 0; t < 8; t++)
        mx = fmaxf(mx, fmaxf(fmaxf(v[t].x, v[t].y), fmaxf(v[t].z, v[t].w)));
#pragma unroll
    for (int off = 16; off >= 1; off >>= 1)
        mx = fmaxf(mx, __shfl_xor_sync(0xffffffffu, mx, off));
    float ssum = 0.f;
#pragma unroll
    for (int t = 0; t < 8; t++) {
        v[t].x = __expf(v[t].x - mx); v[t].y = __expf(v[t].y - mx);
        v[t].z = __expf(v[t].z - mx); v[t].w = __expf(v[t].w - mx);
        ssum += v[t].x + v[t].y + v[t].z + v[t].w;
    }
#pragma unroll
    for (int off = 16; off >= 1; off >>= 1)
        ssum += __shfl_xor_sync(0xffffffffu, ssum, off);
    float inv = 1.f / ssum;

    __half* pr = g_probs + ((size_t)(i * 8 + h)) * 1024;
#pragma unroll
    for (int t = 0; t < 8; t++) {
        __half2 ha = __floats2half2_rn(v[t].x * inv, v[t].y * inv);
        __half2 hb = __floats2half2_rn(v[t].z * inv, v[t].w * inv);
        *(uint2*)&pr[(t * 32 + lane) * 4] = make_uint2(h2u(ha), h2u(hb));
    }
}

// ---------------- K3b: AV via tensor cores + skip + relu ----------------
// Grid (16, 8): CTA = 64 i-rows x head h. 8 warps = 4 m-tiles(16) x 2 n-tiles(8), full k=1024.
// P chunks (64x128 fp16, stride 136) cp.async double-buffered from L2-resident g_probs.
// V_h staged once transposed: Vs[c][k], stride 1032 halfs (conflict-free B frags).
__global__ __launch_bounds__(256) void k3b_av(float* __restrict__ out) {
    extern __shared__ __half s3h[];
    __half* Vs = s3h;                     // 16 * 1032 halfs = 33,024 B
    __half* Ps = s3h + 16 * 1032;         // 2 * 64*136 halfs = 34,816 B

    int i0 = blockIdx.x * 64, h = blockIdx.y;
    int tid = threadIdx.x, lane = tid & 31, warp = tid >> 5;
    int mt = warp & 3, nh = warp >> 2;
    int ro = lane >> 2, kq = lane & 3;

    // stage V_h transposed: Vs[c][j] = fp16(g_vals[j*128 + h*16 + c])
    for (int e = tid; e < 8192; e += 256) {
        int j = e >> 3, cp = e & 7;
        float2 v = *(const float2*)&g_vals[(size_t)j * 128 + h * 16 + 2 * cp];
        Vs[(2 * cp) * 1032 + j]     = __float2half_rn(v.x);
        Vs[(2 * cp + 1) * 1032 + j] = __float2half_rn(v.y);
    }

    auto stage_chunk = [&](int t, int buf) {
#pragma unroll
        for (int it = 0; it < 4; it++) {
            int e = it * 256 + tid;
            int r = e >> 4, s = e & 15;
            const __half* src = g_probs + ((size_t)(i0 + r) * 8 + h) * 1024 + t * 128 + s * 8;
            cp16h(Ps + buf * 8704 + r * 136 + s * 8, src);
        }
        cp_commit();
    };

    stage_chunk(0, 0);

    float c[2][4] = {};   // [n-tile? no: single n-tile] rows (ro, ro+8) x cols (2kq, 2kq+1)
    // c[0][0..3] used as the 4 accumulator regs of the single m16n8 tile
    float acc0 = 0.f, acc1 = 0.f, acc2 = 0.f, acc3 = 0.f;
    (void)c;

    int buf = 0;
    for (int t = 0; t < 8; t++) {
        if (t < 7) stage_chunk(t + 1, buf ^ 1);
        if (t < 7) cp_wait1(); else cp_wait0();
        __syncthreads();

        const __half* Pb = Ps + buf * 8704;
#pragma unroll
        for (int ks = 0; ks < 8; ks++) {
            int kf = ks * 16 + 2 * kq;
            int r0 = (mt * 16 + ro) * 136 + kf;
            unsigned a0 = *(const unsigned*)(Pb + r0);
            unsigned a1 = *(const unsigned*)(Pb + r0 + 1088);   // row +8
            unsigned a2 = *(const unsigned*)(Pb + r0 + 8);      // k +8
            unsigned a3 = *(const unsigned*)(Pb + r0 + 1096);
            const __half* bp = Vs + (nh * 8 + ro) * 1032 + t * 128 + kf;
            unsigned b0 = *(const unsigned*)bp;
            unsigned b1 = *(const unsigned*)(bp + 8);
            asm volatile(
                "mma.sync.aligned.m16n8k16.row.col.f32.f16.f16.f32 "
                "{%0,%1,%2,%3}, {%4,%5,%6,%7}, {%8,%9}, {%0,%1,%2,%3};"
                : "+f"(acc0), "+f"(acc1), "+f"(acc2), "+f"(acc3)
                : "r"(a0), "r"(a1), "r"(a2), "r"(a3), "r"(b0), "r"(b1));
        }
        __syncthreads();
        buf ^= 1;
    }

    // epilogue: + skip, relu, store. rows (ro, ro+8), cols (2kq, 2kq+1) of head h.
    int row0 = i0 + mt * 16 + ro;
    int col = h * 16 + nh * 8 + 2 * kq;
    {
        float2 sk = *(const float2*)&g_skip[(size_t)row0 * 128 + col];
        float2 o;
        o.x = fmaxf(acc0 + sk.x, 0.f);
        o.y = fmaxf(acc1 + sk.y, 0.f);
        *(float2*)&out[(size_t)row0 * 128 + col] = o;
    }
    {
        float2 sk = *(const float2*)&g_skip[(size_t)(row0 + 8) * 128 + col];
        float2 o;
        o.x = fmaxf(acc2 + sk.x, 0.f);
        o.y = fmaxf(acc3 + sk.y, 0.f);
        *(float2*)&out[(size_t)(row0 + 8) * 128 + col] = o;
    }
}

// ---------------- launch ----------------
extern "C" void kernel_launch(void* const* d_in, const int* in_sizes, int n_in,
                              void* d_out, int out_size) {
    const float* node   = (const float*)d_in[0];
    const float* edge   = (const float*)d_in[1];
    const float* graph  = (const float*)d_in[2];
    const int*   adj    = (const int*)  d_in[3];
    const float* hidden = (const float*)d_in[4];
    const float* Wm     = (const float*)d_in[5];
    const float* bm     = (const float*)d_in[6];
    const float* Wskip  = (const float*)d_in[7];
    const float* bskip  = (const float*)d_in[8];
    const float* W1     = (const float*)d_in[9];
    const float* b1     = (const float*)d_in[10];
    const float* W2     = (const float*)d_in[11];
    const float* b2     = (const float*)d_in[12];
    const float* We     = (const float*)d_in[13];
    const float* be     = (const float*)d_in[14];
    const float* Wg     = (const float*)d_in[15];
    const float* bg     = (const float*)d_in[16];
    const float* Aw     = (const float*)d_in[17];
    const float* Abv    = (const float*)d_in[18];
    float* out = (float*)d_out;

    k1_fused<<<dim3(64, 4), 256>>>(node, hidden, graph, Wg, bg, be,
                                   Wm, bm, Wskip, bskip, W1, b1, W2, b2);

    const int smem2 = (3 * 5120 + 128 * 136) * sizeof(__half);   // 65,536 B
    cudaFuncSetAttribute(k2_logits, cudaFuncAttributeMaxDynamicSharedMemorySize, smem2);
    k2_logits<<<296, 256, smem2>>>(edge, We, Aw, Abv, adj);

    k3a_softmax<<<1024, 256>>>();

    const int smem3 = (16 * 1032 + 2 * 64 * 136) * sizeof(__half);   // 67,840 B
    cudaFuncSetAttribute(k3b_av, cudaFuncAttributeMaxDynamicSharedMemorySize, smem3);
    k3b_av<<<dim3(16, 8), 256, smem3>>>(out);
}